// round 10
// baseline (speedup 1.0000x reference)
#include <cuda_runtime.h>
#include <math.h>

#define NB 8       // batch
#define NS 5       // max slabs reachable (spans in [0,5])
#define NSFULL 6   // slab dimension of the input tensor
#define NM 64      // M
#define NV 32000   // vocab
#define NT 8       // template length
#define VSPLIT 8
#define CHUNK   (NV / VSPLIT)    // 4000 floats
#define CHUNK4  (CHUNK / 4)      // 1000 float4
#define HALF4   (CHUNK4 / 2)     // 500 float4 per half
#define NHITER  4                // ceil(500/128)
#define SSTRIDE4 ((NM * NV) / 4) // float4 stride between slabs
#define NBLK   1024              // all co-resident (128 thr, <=7/SM)
#define NPAIR  (NB / 2)          // 4 batch pairs

// tiny scratch (__device__ globals, no runtime allocation)
__device__ float    g_pmax[NB * NT * NM * VSPLIT * 2];  // per-(chunk,half) max
__device__ float    g_out0[NB * NT * NM];               // out[b,t,m,0] (+pad)
__device__ unsigned g_count;                            // barrier arrivals
__device__ unsigned g_sense;                            // barrier sense (monotonic)

// ---------------------------------------------------------------------------
// Grid-wide barrier (all NBLK blocks co-resident; launch_bounds(128,7) =>
// 148*7=1036 >= 1024). Sense monotonic (replay-safe); count self-resets.
// ---------------------------------------------------------------------------
__device__ __forceinline__ void grid_barrier() {
    __syncthreads();
    __threadfence();
    if (threadIdx.x == 0) {
        const unsigned s0 = *(volatile unsigned*)&g_sense;
        const unsigned v  = atomicAdd(&g_count, 1);
        if (v == NBLK - 1) {
            g_count = 0;
            __threadfence();
            atomicAdd(&g_sense, 1);
        } else {
            while (*(volatile unsigned*)&g_sense == s0) { __nanosleep(64); }
        }
    }
    __syncthreads();
    __threadfence();
}

// ---------------------------------------------------------------------------
// Phase A half-chunk body, compile-time S: max over 500 float4 for each t.
// ---------------------------------------------------------------------------
template <int S>
__device__ __forceinline__ void phase_a_body(
    const float4* __restrict__ p0,
    const float (&sw)[NT][NS], float (&maxv)[NT]) {

    const int tid = threadIdx.x;
    #pragma unroll
    for (int t = 0; t < NT; t++) maxv[t] = -INFINITY;

    #pragma unroll
    for (int j = 0; j < NHITER; j++) {
        const int i = tid + j * 128;
        if (i < HALF4) {
            float4 x[S > 0 ? S : 1];
            #pragma unroll
            for (int s = 0; s < S; s++) x[s] = p0[i + s * SSTRIDE4];

            #pragma unroll
            for (int t = 0; t < NT; t++) {
                float ax = 0.f, ay = 0.f, az = 0.f, aw = 0.f;
                #pragma unroll
                for (int s = 0; s < S; s++) {
                    const float wv = sw[t][s];
                    ax = fmaf(wv, x[s].x, ax);
                    ay = fmaf(wv, x[s].y, ay);
                    az = fmaf(wv, x[s].z, az);
                    aw = fmaf(wv, x[s].w, aw);
                }
                maxv[t] = fmaxf(maxv[t], fmaxf(fmaxf(ax, ay), fmaxf(az, aw)));
            }
        }
    }
}

// ---------------------------------------------------------------------------
// Phase C half-row body, compile-time S, streaming stores.
// ---------------------------------------------------------------------------
template <int S>
__device__ __forceinline__ void phase_c_body(
    const float4* __restrict__ p0, float4* __restrict__ dst,
    const float (&ws)[NS], float w0, int ml, int first_half) {

    const int tid = threadIdx.x;
    #pragma unroll
    for (int j = 0; j < NHITER; j++) {
        const int i = tid + j * 128;
        if (i < HALF4) {
            float4 x[S > 0 ? S : 1];
            #pragma unroll
            for (int s = 0; s < S; s++) x[s] = p0[i + s * SSTRIDE4];

            float4 acc = make_float4(0.f, 0.f, 0.f, 0.f);
            #pragma unroll
            for (int s = 0; s < S; s++) {
                const float wv = ws[s];
                acc.x = fmaf(wv, x[s].x, acc.x);
                acc.y = fmaf(wv, x[s].y, acc.y);
                acc.z = fmaf(wv, x[s].z, acc.z);
                acc.w = fmaf(wv, x[s].w, acc.w);
            }
            if (first_half && i == 0 && ml == 0) acc.x += w0;  // pad one-hot
            __stcs(dst + i, acc);
        }
    }
}

// ---------------------------------------------------------------------------
// Fused persistent kernel, batch-split balancing:
// block (m, yb, chunk) handles half yb of batch 2p and half yb^1 of 2p+1,
// so per-block load volume is (S0+S1)*500 float4 — uniform over the grid.
// argmax==0  <=>  out[v=0] attains the max (argmax ties go to index 0)
// ---------------------------------------------------------------------------
__global__ void __launch_bounds__(128, 7)
fused_kernel(const float* __restrict__ in, const float* __restrict__ tmpl,
             const int* __restrict__ spans, float* __restrict__ out) {
    const int m     = blockIdx.x;   // A row / C output row
    const int yb    = blockIdx.y;   // half selector
    const int chunk = blockIdx.z;
    const int tid   = threadIdx.x;

    __shared__ float spart[4][NT];
    __shared__ unsigned char sflags[2][NT * NM];
    __shared__ unsigned char slen[2][NT];
    __shared__ short         srow[2][NM];

    for (int p = 0; p < NPAIR; p++) {
        // ================= phase A: two half-chunk sub-phases =================
        #pragma unroll
        for (int q = 0; q < 2; q++) {
            const int b = 2 * p + q;
            const int h = yb ^ q;
            const int S = __ldg(&spans[b]);

            float sw[NT][NS];
            #pragma unroll
            for (int t = 0; t < NT; t++)
                #pragma unroll
                for (int s = 0; s < NS; s++)
                    sw[t][s] = __ldg(&tmpl[((size_t)b * NT + t) * (NSFULL + 1) + s + 1]);

            const float4* pa = reinterpret_cast<const float4*>(
                in + ((size_t)b * NSFULL * NM + m) * NV + chunk * CHUNK) + h * HALF4;

            float maxv[NT];
            switch (S) {
                case 0: phase_a_body<0>(pa, sw, maxv); break;
                case 1: phase_a_body<1>(pa, sw, maxv); break;
                case 2: phase_a_body<2>(pa, sw, maxv); break;
                case 3: phase_a_body<3>(pa, sw, maxv); break;
                case 4: phase_a_body<4>(pa, sw, maxv); break;
                default: phase_a_body<5>(pa, sw, maxv); break;
            }

            #pragma unroll
            for (int t = 0; t < NT; t++) {
                float v = maxv[t];
                #pragma unroll
                for (int off = 16; off > 0; off >>= 1)
                    v = fmaxf(v, __shfl_xor_sync(0xFFFFFFFFu, v, off));
                maxv[t] = v;
            }
            const int warp = tid >> 5, lane = tid & 31;
            __syncthreads();                        // spart reuse across q
            if (lane == 0) {
                #pragma unroll
                for (int t = 0; t < NT; t++) spart[warp][t] = maxv[t];
            }
            __syncthreads();
            if (tid < NT) {
                const int t = tid;
                float mx = fmaxf(fmaxf(spart[0][t], spart[1][t]),
                                 fmaxf(spart[2][t], spart[3][t]));
                g_pmax[((((size_t)b * NT + t) * NM + m) * VSPLIT + chunk) * 2 + h] = mx;
            }

            // cold epilogue: out[b,t,m,0] (dot + pad), from the h==0/chunk==0 block
            if (chunk == 0 && h == 0 && tid == 0) {
                float x0[NS + 1];
                for (int s = 0; s < S; s++)
                    x0[s] = reinterpret_cast<const float*>(pa + s * SSTRIDE4)[0];
                #pragma unroll
                for (int t = 0; t < NT; t++) {
                    float v = 0.f;
                    for (int s = 0; s < S; s++) v = fmaf(sw[t][s], x0[s], v);
                    if (m == 0)
                        v += __ldg(&tmpl[((size_t)b * NT + t) * (NSFULL + 1)]);
                    g_out0[((size_t)b * NT + t) * NM + m] = v;
                }
            }
        }

        // all A_p results visible before any C_p scan
        grid_barrier();

        // ================= phase C: build both scan maps, write two halves ====
        #pragma unroll
        for (int q = 0; q < 2; q++) {
            const int b = 2 * p + q;
            #pragma unroll
            for (int k = 0; k < 4; k++) {
                const int tm  = tid + 128 * k;              // t*64 + mm
                const int idx = b * NT * NM + tm;
                const float4* pm = reinterpret_cast<const float4*>(
                    &g_pmax[(size_t)idx * (VSPLIT * 2)]);
                float mx = -INFINITY;
                #pragma unroll
                for (int r = 0; r < 4; r++) {
                    const float4 a = __ldcg(pm + r);
                    mx = fmaxf(mx, fmaxf(fmaxf(a.x, a.y), fmaxf(a.z, a.w)));
                }
                sflags[q][tm] = (__ldcg(&g_out0[idx]) >= mx) ? 1 : 0;
            }
        }
        __syncthreads();
        if (tid < 2 * NT) {                                 // first-zero per (q,t)
            const int q = tid >> 3, t = tid & 7;
            int len = NM;
            for (int mm = 0; mm < NM; mm++)
                if (sflags[q][t * NM + mm]) { len = mm; break; }
            slen[q][t] = (unsigned char)len;
        }
        __syncthreads();
        if (tid < 2) {                                      // sequential scan
            const int q = tid;
            for (int r = 0; r < NM; r++) srow[q][r] = -1;
            int idx = 0;
            for (int t = 0; t < NT; t++) {
                int len = slen[q][t];
                if (len > NM - idx) len = NM - idx;
                for (int k = 0; k < len; k++)
                    srow[q][idx + k] = (short)((t << 8) | k);
                idx += len;
            }
        }
        __syncthreads();

        #pragma unroll
        for (int q = 0; q < 2; q++) {
            const int b = 2 * p + q;
            const int h = yb ^ q;
            const int first_half = (chunk == 0 && h == 0);

            float4* dst = reinterpret_cast<float4*>(
                out + ((size_t)b * NM + m) * NV + chunk * CHUNK) + h * HALF4;
            const int code = srow[q][m];

            if (code < 0) {
                const float4 z = make_float4(0.f, 0.f, 0.f, 0.f);
                #pragma unroll
                for (int jj = 0; jj < NHITER; jj++) {
                    const int i = tid + jj * 128;
                    if (i < HALF4) __stcs(dst + i, z);
                }
            } else {
                const int t  = code >> 8;
                const int ml = code & 255;
                const int S  = __ldg(&spans[b]);

                float ws[NS];
                #pragma unroll
                for (int s = 0; s < NS; s++)
                    ws[s] = __ldg(&tmpl[((size_t)b * NT + t) * (NSFULL + 1) + s + 1]);
                const float w0 = __ldg(&tmpl[((size_t)b * NT + t) * (NSFULL + 1)]);

                const float4* pc = reinterpret_cast<const float4*>(
                    in + ((size_t)b * NSFULL * NM + ml) * NV + chunk * CHUNK) + h * HALF4;

                switch (S) {
                    case 0: phase_c_body<0>(pc, dst, ws, w0, ml, first_half); break;
                    case 1: phase_c_body<1>(pc, dst, ws, w0, ml, first_half); break;
                    case 2: phase_c_body<2>(pc, dst, ws, w0, ml, first_half); break;
                    case 3: phase_c_body<3>(pc, dst, ws, w0, ml, first_half); break;
                    case 4: phase_c_body<4>(pc, dst, ws, w0, ml, first_half); break;
                    default: phase_c_body<5>(pc, dst, ws, w0, ml, first_half); break;
                }
            }
        }
        __syncthreads();   // sflags/srow reuse next pair
        // no global barrier before next A: scratch indices disjoint across pairs.
    }
}

// ---------------------------------------------------------------------------
extern "C" void kernel_launch(void* const* d_in, const int* in_sizes, int n_in,
                              void* d_out, int out_size) {
    const float* in    = (const float*)d_in[0];  // [8,6,64,32000] f32
    const float* tmpl  = (const float*)d_in[1];  // [8,8,7] f32
    const int*   spans = (const int*)d_in[2];    // [8] i32
    float*       out   = (float*)d_out;          // [8,64,32000] f32

    dim3 grid(NM, 2, VSPLIT);  // 1024 blocks, one resident wave
    fused_kernel<<<grid, 128>>>(in, tmpl, spans, out);
}

// round 11
// speedup vs baseline: 1.6238x; 1.6238x over previous
#include <cuda_runtime.h>
#include <math.h>

#define NB 8       // batch
#define NS 5       // max slabs reachable (spans in [0,5])
#define NSFULL 6   // slab dimension of the input tensor
#define NM 64      // M
#define NV 32000   // vocab
#define NT 8       // template length
#define VSPLIT 8
#define CHUNK  (NV / VSPLIT)   // 4000 floats
#define CHUNK4 (CHUNK / 4)     // 1000 float4
#define NITER  ((CHUNK4 + 127) / 128)   // 8
#define SSTRIDE4 ((NM * NV) / 4)        // float4 stride between slabs
#define NBLK   1024                     // all co-resident (128 thr, <=7/SM)
#define NPAIR  (NB / 2)                 // 4 batch pairs

// tiny scratch (__device__ globals, no runtime allocation)
__device__ float    g_pmax[NB * NT * NM * VSPLIT];  // per-chunk partial max
__device__ float    g_out0[NB * NT * NM];           // out[b,t,m,0] (+pad)
__device__ int      g_rowmap[NB * NM];              // (t<<8)|ml, or -1
__device__ unsigned g_count;                        // barrier arrivals (self-resets)
__device__ unsigned g_sense;                        // barrier sense (monotonic)

// ---------------------------------------------------------------------------
// Grid-wide barrier (all NBLK blocks co-resident; launch_bounds(128,7) =>
// 148*7 = 1036 >= 1024). Sense monotonic (replay-safe); count self-resets.
// ---------------------------------------------------------------------------
__device__ __forceinline__ void grid_barrier() {
    __syncthreads();
    __threadfence();
    if (threadIdx.x == 0) {
        const unsigned s0 = *(volatile unsigned*)&g_sense;
        const unsigned v  = atomicAdd(&g_count, 1);
        if (v == NBLK - 1) {
            g_count = 0;
            __threadfence();
            atomicAdd(&g_sense, 1);
        } else {
            while (*(volatile unsigned*)&g_sense == s0) { __nanosleep(64); }
        }
    }
    __syncthreads();
    __threadfence();
}

// ---------------------------------------------------------------------------
// Phase A body, compile-time S: per-(b,m,chunk) max over v for each t.
// ---------------------------------------------------------------------------
template <int S>
__device__ __forceinline__ void phase_a_body(
    const float4* __restrict__ p0, int b, int m, int chunk,
    const float (&sw)[NT][NS], const float (&sw0)[NT], float (&maxv)[NT]) {

    const int tid = threadIdx.x;
    #pragma unroll
    for (int t = 0; t < NT; t++) maxv[t] = -INFINITY;

    #pragma unroll 2
    for (int j = 0; j < NITER; j++) {
        const int i = tid + j * 128;
        if (i < CHUNK4) {
            float4 x[S > 0 ? S : 1];
            #pragma unroll
            for (int s = 0; s < S; s++) x[s] = p0[i + s * SSTRIDE4];

            #pragma unroll
            for (int t = 0; t < NT; t++) {
                float ax = 0.f, ay = 0.f, az = 0.f, aw = 0.f;
                #pragma unroll
                for (int s = 0; s < S; s++) {
                    const float wv = sw[t][s];
                    ax = fmaf(wv, x[s].x, ax);
                    ay = fmaf(wv, x[s].y, ay);
                    az = fmaf(wv, x[s].z, az);
                    aw = fmaf(wv, x[s].w, aw);
                }
                maxv[t] = fmaxf(maxv[t], fmaxf(fmaxf(ax, ay), fmaxf(az, aw)));
            }
        }
    }

    // cold epilogue: out[b,t,m,0] (dot + pad one-hot), chunk 0 / thread 0 only
    if (chunk == 0 && tid == 0) {
        float x0[S > 0 ? S : 1];
        #pragma unroll
        for (int s = 0; s < S; s++)
            x0[s] = reinterpret_cast<const float*>(p0 + s * SSTRIDE4)[0];
        #pragma unroll
        for (int t = 0; t < NT; t++) {
            float v = 0.f;
            #pragma unroll
            for (int s = 0; s < S; s++) v = fmaf(sw[t][s], x0[s], v);
            if (m == 0) v += sw0[t];
            g_out0[((size_t)b * NT + t) * NM + m] = v;
        }
    }
}

// ---------------------------------------------------------------------------
// Phase C body, compile-time S, streaming stores.
// ---------------------------------------------------------------------------
template <int S>
__device__ __forceinline__ void phase_c_body(
    const float4* __restrict__ p0, float4* __restrict__ dst,
    const float (&ws)[NS], float w0, int ml, int chunk) {

    const int tid = threadIdx.x;
    #pragma unroll 2
    for (int j = 0; j < NITER; j++) {
        const int i = tid + j * 128;
        if (i < CHUNK4) {
            float4 x[S > 0 ? S : 1];
            #pragma unroll
            for (int s = 0; s < S; s++) x[s] = p0[i + s * SSTRIDE4];

            float4 acc = make_float4(0.f, 0.f, 0.f, 0.f);
            #pragma unroll
            for (int s = 0; s < S; s++) {
                const float wv = ws[s];
                acc.x = fmaf(wv, x[s].x, acc.x);
                acc.y = fmaf(wv, x[s].y, acc.y);
                acc.z = fmaf(wv, x[s].z, acc.z);
                acc.w = fmaf(wv, x[s].w, acc.w);
            }
            if (chunk == 0 && i == 0 && ml == 0) acc.x += w0;  // pad one-hot
            __stcs(dst + i, acc);
        }
    }
}

// ---------------------------------------------------------------------------
// Fused persistent kernel:
//   A_p -> barrier -> 2 scan blocks build g_rowmap -> barrier -> C_p.
// argmax==0  <=>  out[v=0] attains the max (argmax ties go to index 0)
// ---------------------------------------------------------------------------
__global__ void __launch_bounds__(128, 7)
fused_kernel(const float* __restrict__ in, const float* __restrict__ tmpl,
             const int* __restrict__ spans, float* __restrict__ out) {
    const int m     = blockIdx.x;   // row index in A, output row j in C
    const int yb    = blockIdx.y;   // 0/1 within the pair
    const int chunk = blockIdx.z;
    const int tid   = threadIdx.x;
    const bool is_scan_blk = (m == 0 && chunk == 0);

    __shared__ float ssw[NT][NS];
    __shared__ float ssw0[NT];
    __shared__ int   sS;
    __shared__ float spart[4][NT];
    __shared__ unsigned char sflags[NT * NM];   // scan blocks only
    __shared__ unsigned char slen[NT];
    __shared__ short         srow[NM];

    for (int p = 0; p < NPAIR; p++) {
        const int b = 2 * p + yb;
        __syncthreads();   // protect shared arrays across iterations

        // ---- stage weights for batch b ----
        if (tid == 0) sS = spans[b];
        if (tid < NT * NSFULL) {
            int t = tid / NSFULL, s = tid % NSFULL;
            float v = tmpl[((size_t)b * NT + t) * (NSFULL + 1) + s];
            if (s == 0) ssw0[t] = v;
            else        ssw[t][s - 1] = v;
        }
        __syncthreads();
        const int S = sS;

        float sw[NT][NS], sw0[NT];
        #pragma unroll
        for (int t = 0; t < NT; t++) {
            sw0[t] = ssw0[t];
            #pragma unroll
            for (int s = 0; s < NS; s++) sw[t][s] = ssw[t][s];
        }

        const float4* pa = reinterpret_cast<const float4*>(
            in + ((size_t)b * NSFULL * NM + m) * NV + chunk * CHUNK);

        // ---- phase A ----
        float maxv[NT];
        switch (S) {
            case 0: phase_a_body<0>(pa, b, m, chunk, sw, sw0, maxv); break;
            case 1: phase_a_body<1>(pa, b, m, chunk, sw, sw0, maxv); break;
            case 2: phase_a_body<2>(pa, b, m, chunk, sw, sw0, maxv); break;
            case 3: phase_a_body<3>(pa, b, m, chunk, sw, sw0, maxv); break;
            case 4: phase_a_body<4>(pa, b, m, chunk, sw, sw0, maxv); break;
            default: phase_a_body<5>(pa, b, m, chunk, sw, sw0, maxv); break;
        }

        #pragma unroll
        for (int t = 0; t < NT; t++) {
            float v = maxv[t];
            #pragma unroll
            for (int off = 16; off > 0; off >>= 1)
                v = fmaxf(v, __shfl_xor_sync(0xFFFFFFFFu, v, off));
            maxv[t] = v;
        }
        const int warp = tid >> 5, lane = tid & 31;
        if (lane == 0) {
            #pragma unroll
            for (int t = 0; t < NT; t++) spart[warp][t] = maxv[t];
        }
        __syncthreads();
        if (tid < NT) {
            const int t = tid;
            float mx = fmaxf(fmaxf(spart[0][t], spart[1][t]),
                             fmaxf(spart[2][t], spart[3][t]));
            g_pmax[(((size_t)b * NT + t) * NM + m) * VSPLIT + chunk] = mx;
        }

        // ---- barrier 1: all maxes visible ----
        grid_barrier();

        // ---- dedicated scan blocks (2 per pair: one per batch) ----
        if (is_scan_blk) {
            #pragma unroll
            for (int k = 0; k < 4; k++) {
                const int tm  = tid + 128 * k;              // t*64 + mm
                const int idx = b * NT * NM + tm;
                const float4* pm =
                    reinterpret_cast<const float4*>(&g_pmax[(size_t)idx * VSPLIT]);
                const float4 a = __ldcg(pm), c = __ldcg(pm + 1);
                float mx = fmaxf(fmaxf(fmaxf(a.x, a.y), fmaxf(a.z, a.w)),
                                 fmaxf(fmaxf(c.x, c.y), fmaxf(c.z, c.w)));
                sflags[tm] = (__ldcg(&g_out0[idx]) >= mx) ? 1 : 0;
            }
            __syncthreads();
            if (tid < NT) {     // first-zero position per t
                int len = NM;
                for (int mm = 0; mm < NM; mm++)
                    if (sflags[tid * NM + mm]) { len = mm; break; }
                slen[tid] = (unsigned char)len;
            }
            __syncthreads();
            if (tid == 0) {     // sequential scan -> row map
                for (int q = 0; q < NM; q++) srow[q] = -1;
                int idx = 0;
                for (int t = 0; t < NT; t++) {
                    int len = slen[t];
                    if (len > NM - idx) len = NM - idx;
                    for (int k = 0; k < len; k++)
                        srow[idx + k] = (short)((t << 8) | k);
                    idx += len;
                }
            }
            __syncthreads();
            if (tid < NM) g_rowmap[b * NM + tid] = srow[tid];
        }

        // ---- barrier 2: g_rowmap visible ----
        grid_barrier();

        // ---- phase C: materialize this block's output row (j = m) ----
        const int code = g_rowmap[b * NM + m];
        float4* dst = reinterpret_cast<float4*>(
            out + ((size_t)b * NM + m) * NV + chunk * CHUNK);

        if (code < 0) {
            const float4 z = make_float4(0.f, 0.f, 0.f, 0.f);
            #pragma unroll 2
            for (int jj = 0; jj < NITER; jj++) {
                const int i = tid + jj * 128;
                if (i < CHUNK4) __stcs(dst + i, z);
            }
        } else {
            const int t  = code >> 8;
            const int ml = code & 255;

            float ws[NS];
            #pragma unroll
            for (int s = 0; s < NS; s++)
                ws[s] = __ldg(&tmpl[((size_t)b * NT + t) * (NSFULL + 1) + s + 1]);
            const float w0 = __ldg(&tmpl[((size_t)b * NT + t) * (NSFULL + 1)]);

            const float4* pc = reinterpret_cast<const float4*>(
                in + ((size_t)b * NSFULL * NM + ml) * NV + chunk * CHUNK);

            switch (S) {
                case 0: phase_c_body<0>(pc, dst, ws, w0, ml, chunk); break;
                case 1: phase_c_body<1>(pc, dst, ws, w0, ml, chunk); break;
                case 2: phase_c_body<2>(pc, dst, ws, w0, ml, chunk); break;
                case 3: phase_c_body<3>(pc, dst, ws, w0, ml, chunk); break;
                case 4: phase_c_body<4>(pc, dst, ws, w0, ml, chunk); break;
                default: phase_c_body<5>(pc, dst, ws, w0, ml, chunk); break;
            }
        }
        // no barrier before next A: scratch indices disjoint across pairs;
        // shared arrays protected by loop-top __syncthreads.
    }
}

// ---------------------------------------------------------------------------
extern "C" void kernel_launch(void* const* d_in, const int* in_sizes, int n_in,
                              void* d_out, int out_size) {
    const float* in    = (const float*)d_in[0];  // [8,6,64,32000] f32
    const float* tmpl  = (const float*)d_in[1];  // [8,8,7] f32
    const int*   spans = (const int*)d_in[2];    // [8] i32
    float*       out   = (float*)d_out;          // [8,64,32000] f32

    dim3 grid(NM, 2, VSPLIT);  // 1024 blocks, exactly one resident wave
    fused_kernel<<<grid, 128>>>(in, tmpl, spans, out);
}

// round 12
// speedup vs baseline: 1.6949x; 1.0438x over previous
#include <cuda_runtime.h>
#include <math.h>

#define NB 8       // batch
#define NS 5       // max slabs reachable (spans in [0,5])
#define NSFULL 6   // slab dimension of the input tensor
#define NM 64      // M
#define NV 32000   // vocab
#define NT 8       // template length
#define VSPLIT 8
#define CHUNK  (NV / VSPLIT)   // 4000 floats
#define CHUNK4 (CHUNK / 4)     // 1000 float4
#define NITER  ((CHUNK4 + 127) / 128)   // 8
#define SSTRIDE4 ((NM * NV) / 4)        // float4 stride between slabs
#define NBLK   1024                     // all co-resident (128 thr, <=7/SM)
#define NPAIR  (NB / 2)                 // 4 batch pairs

// tiny scratch (__device__ globals, no runtime allocation)
__device__ float    g_pmax[NB * NT * NM * VSPLIT];  // per-chunk partial max
__device__ float    g_out0[NB * NT * NM];           // out[b,t,m,0] (+pad)
__device__ unsigned g_count;                        // barrier arrivals (self-resets)
__device__ unsigned g_sense;                        // barrier sense (monotonic)

// ---------------------------------------------------------------------------
// Grid-wide barrier (all NBLK blocks co-resident; launch_bounds(128,7) =>
// 148*7 = 1036 >= 1024). Sense monotonic (replay-safe); count self-resets.
// ---------------------------------------------------------------------------
__device__ __forceinline__ void grid_barrier() {
    __syncthreads();
    __threadfence();
    if (threadIdx.x == 0) {
        const unsigned s0 = *(volatile unsigned*)&g_sense;
        const unsigned v  = atomicAdd(&g_count, 1);
        if (v == NBLK - 1) {
            g_count = 0;
            __threadfence();
            atomicAdd(&g_sense, 1);
        } else {
            while (*(volatile unsigned*)&g_sense == s0) { __nanosleep(64); }
        }
    }
    __syncthreads();
    __threadfence();
}

// ---------------------------------------------------------------------------
// Phase A body, compile-time S: per-(b,m,chunk) max over v for each t.
// ---------------------------------------------------------------------------
template <int S>
__device__ __forceinline__ void phase_a_body(
    const float4* __restrict__ p0, int b, int m, int chunk,
    const float (&sw)[NT][NS], const float (&sw0)[NT], float (&maxv)[NT]) {

    const int tid = threadIdx.x;
    #pragma unroll
    for (int t = 0; t < NT; t++) maxv[t] = -INFINITY;

    #pragma unroll 2
    for (int j = 0; j < NITER; j++) {
        const int i = tid + j * 128;
        if (i < CHUNK4) {
            float4 x[S > 0 ? S : 1];
            #pragma unroll
            for (int s = 0; s < S; s++) x[s] = p0[i + s * SSTRIDE4];

            #pragma unroll
            for (int t = 0; t < NT; t++) {
                float ax = 0.f, ay = 0.f, az = 0.f, aw = 0.f;
                #pragma unroll
                for (int s = 0; s < S; s++) {
                    const float wv = sw[t][s];
                    ax = fmaf(wv, x[s].x, ax);
                    ay = fmaf(wv, x[s].y, ay);
                    az = fmaf(wv, x[s].z, az);
                    aw = fmaf(wv, x[s].w, aw);
                }
                maxv[t] = fmaxf(maxv[t], fmaxf(fmaxf(ax, ay), fmaxf(az, aw)));
            }
        }
    }

    // cold epilogue: out[b,t,m,0] (dot + pad one-hot), chunk 0 / thread 0 only
    if (chunk == 0 && tid == 0) {
        float x0[S > 0 ? S : 1];
        #pragma unroll
        for (int s = 0; s < S; s++)
            x0[s] = reinterpret_cast<const float*>(p0 + s * SSTRIDE4)[0];
        #pragma unroll
        for (int t = 0; t < NT; t++) {
            float v = 0.f;
            #pragma unroll
            for (int s = 0; s < S; s++) v = fmaf(sw[t][s], x0[s], v);
            if (m == 0) v += sw0[t];
            g_out0[((size_t)b * NT + t) * NM + m] = v;
        }
    }
}

// ---------------------------------------------------------------------------
// Phase C body, compile-time S, streaming stores.
// ---------------------------------------------------------------------------
template <int S>
__device__ __forceinline__ void phase_c_body(
    const float4* __restrict__ p0, float4* __restrict__ dst,
    const float (&ws)[NS], float w0, int ml, int chunk) {

    const int tid = threadIdx.x;
    #pragma unroll 2
    for (int j = 0; j < NITER; j++) {
        const int i = tid + j * 128;
        if (i < CHUNK4) {
            float4 x[S > 0 ? S : 1];
            #pragma unroll
            for (int s = 0; s < S; s++) x[s] = p0[i + s * SSTRIDE4];

            float4 acc = make_float4(0.f, 0.f, 0.f, 0.f);
            #pragma unroll
            for (int s = 0; s < S; s++) {
                const float wv = ws[s];
                acc.x = fmaf(wv, x[s].x, acc.x);
                acc.y = fmaf(wv, x[s].y, acc.y);
                acc.z = fmaf(wv, x[s].z, acc.z);
                acc.w = fmaf(wv, x[s].w, acc.w);
            }
            if (chunk == 0 && i == 0 && ml == 0) acc.x += w0;  // pad one-hot
            __stcs(dst + i, acc);
        }
    }
}

// ---------------------------------------------------------------------------
// Fused persistent kernel: span-sorted pairing, A_p -> barrier -> C_p.
// argmax==0  <=>  out[v=0] attains the max (argmax ties go to index 0)
// ---------------------------------------------------------------------------
__global__ void __launch_bounds__(128, 7)
fused_kernel(const float* __restrict__ in, const float* __restrict__ tmpl,
             const int* __restrict__ spans, float* __restrict__ out) {
    const int m     = blockIdx.x;   // row index in A, output row j in C
    const int yb    = blockIdx.y;   // 0/1 within the pair
    const int chunk = blockIdx.z;
    const int tid   = threadIdx.x;

    __shared__ unsigned char s_order[NB];   // batches sorted by span (asc)
    __shared__ float ssw[NT][NS];
    __shared__ float ssw0[NT];
    __shared__ int   sS;
    __shared__ float spart[4][NT];
    __shared__ unsigned char sflags[NT * NM];
    __shared__ unsigned char slen[NT];
    __shared__ short         srow[NM];

    // deterministic span-sorted batch order (identical in every block):
    // pairing adjacent order statistics minimizes |S0-S1| per pair -> minimal
    // phase-A barrier spin.
    if (tid == 0) {
        int ord[NB], sp[NB];
        #pragma unroll
        for (int i = 0; i < NB; i++) { ord[i] = i; sp[i] = spans[i]; }
        #pragma unroll
        for (int i = 1; i < NB; i++) {        // stable insertion sort
            int oi = ord[i], key = sp[oi], j = i - 1;
            while (j >= 0 && sp[ord[j]] > key) { ord[j + 1] = ord[j]; j--; }
            ord[j + 1] = oi;
        }
        #pragma unroll
        for (int i = 0; i < NB; i++) s_order[i] = (unsigned char)ord[i];
    }
    __syncthreads();

    for (int p = 0; p < NPAIR; p++) {
        const int b = s_order[2 * p + yb];
        __syncthreads();   // protect shared arrays across iterations

        // ---- stage weights for batch b ----
        if (tid == 0) sS = spans[b];
        if (tid < NT * NSFULL) {
            int t = tid / NSFULL, s = tid % NSFULL;
            float v = tmpl[((size_t)b * NT + t) * (NSFULL + 1) + s];
            if (s == 0) ssw0[t] = v;
            else        ssw[t][s - 1] = v;
        }
        __syncthreads();
        const int S = sS;

        float sw[NT][NS], sw0[NT];
        #pragma unroll
        for (int t = 0; t < NT; t++) {
            sw0[t] = ssw0[t];
            #pragma unroll
            for (int s = 0; s < NS; s++) sw[t][s] = ssw[t][s];
        }

        const float4* pa = reinterpret_cast<const float4*>(
            in + ((size_t)b * NSFULL * NM + m) * NV + chunk * CHUNK);

        // ---- phase A ----
        float maxv[NT];
        switch (S) {
            case 0: phase_a_body<0>(pa, b, m, chunk, sw, sw0, maxv); break;
            case 1: phase_a_body<1>(pa, b, m, chunk, sw, sw0, maxv); break;
            case 2: phase_a_body<2>(pa, b, m, chunk, sw, sw0, maxv); break;
            case 3: phase_a_body<3>(pa, b, m, chunk, sw, sw0, maxv); break;
            case 4: phase_a_body<4>(pa, b, m, chunk, sw, sw0, maxv); break;
            default: phase_a_body<5>(pa, b, m, chunk, sw, sw0, maxv); break;
        }

        #pragma unroll
        for (int t = 0; t < NT; t++) {
            float v = maxv[t];
            #pragma unroll
            for (int off = 16; off > 0; off >>= 1)
                v = fmaxf(v, __shfl_xor_sync(0xFFFFFFFFu, v, off));
            maxv[t] = v;
        }
        const int warp = tid >> 5, lane = tid & 31;
        if (lane == 0) {
            #pragma unroll
            for (int t = 0; t < NT; t++) spart[warp][t] = maxv[t];
        }
        __syncthreads();
        if (tid < NT) {
            const int t = tid;
            float mx = fmaxf(fmaxf(spart[0][t], spart[1][t]),
                             fmaxf(spart[2][t], spart[3][t]));
            g_pmax[(((size_t)b * NT + t) * NM + m) * VSPLIT + chunk] = mx;
        }

        // ---- all blocks' maxes must land before anyone scans ----
        grid_barrier();

        // ---- phase C: flags + scan (redundant per block, L2-hot) ----
        #pragma unroll
        for (int k = 0; k < 4; k++) {
            const int tm  = tid + 128 * k;               // t*64 + mm
            const int idx = b * NT * NM + tm;
            const float4* pm =
                reinterpret_cast<const float4*>(&g_pmax[(size_t)idx * VSPLIT]);
            const float4 a = __ldcg(pm), c = __ldcg(pm + 1);
            float mx = fmaxf(fmaxf(fmaxf(a.x, a.y), fmaxf(a.z, a.w)),
                             fmaxf(fmaxf(c.x, c.y), fmaxf(c.z, c.w)));
            sflags[tm] = (__ldcg(&g_out0[idx]) >= mx) ? 1 : 0;
        }
        __syncthreads();

        if (tid < NT) {   // first-zero position per t
            int len = NM;
            for (int mm = 0; mm < NM; mm++)
                if (sflags[tid * NM + mm]) { len = mm; break; }
            slen[tid] = (unsigned char)len;
        }
        __syncthreads();

        if (tid == 0) {   // sequential scan -> row map
            for (int q = 0; q < NM; q++) srow[q] = -1;
            int idx = 0;
            for (int t = 0; t < NT; t++) {
                int len = slen[t];
                if (len > NM - idx) len = NM - idx;
                for (int k = 0; k < len; k++)
                    srow[idx + k] = (short)((t << 8) | k);
                idx += len;
            }
        }
        __syncthreads();

        // ---- phase C: materialize this block's output row (j = m) ----
        float4* dst = reinterpret_cast<float4*>(
            out + ((size_t)b * NM + m) * NV + chunk * CHUNK);
        const int code = srow[m];

        if (code < 0) {
            const float4 z = make_float4(0.f, 0.f, 0.f, 0.f);
            #pragma unroll 2
            for (int jj = 0; jj < NITER; jj++) {
                const int i = tid + jj * 128;
                if (i < CHUNK4) __stcs(dst + i, z);
            }
        } else {
            const int t  = code >> 8;
            const int ml = code & 255;

            float ws[NS];
            #pragma unroll
            for (int s = 0; s < NS; s++)
                ws[s] = tmpl[((size_t)b * NT + t) * (NSFULL + 1) + s + 1];
            const float w0 = tmpl[((size_t)b * NT + t) * (NSFULL + 1) + 0];

            const float4* pc = reinterpret_cast<const float4*>(
                in + ((size_t)b * NSFULL * NM + ml) * NV + chunk * CHUNK);

            switch (S) {
                case 0: phase_c_body<0>(pc, dst, ws, w0, ml, chunk); break;
                case 1: phase_c_body<1>(pc, dst, ws, w0, ml, chunk); break;
                case 2: phase_c_body<2>(pc, dst, ws, w0, ml, chunk); break;
                case 3: phase_c_body<3>(pc, dst, ws, w0, ml, chunk); break;
                case 4: phase_c_body<4>(pc, dst, ws, w0, ml, chunk); break;
                default: phase_c_body<5>(pc, dst, ws, w0, ml, chunk); break;
            }
        }
        // no barrier before next A: g_pmax/g_out0 indices disjoint across
        // pairs; shared arrays protected by loop-top __syncthreads.
    }
}

// ---------------------------------------------------------------------------
extern "C" void kernel_launch(void* const* d_in, const int* in_sizes, int n_in,
                              void* d_out, int out_size) {
    const float* in    = (const float*)d_in[0];  // [8,6,64,32000] f32
    const float* tmpl  = (const float*)d_in[1];  // [8,8,7] f32
    const int*   spans = (const int*)d_in[2];    // [8] i32
    float*       out   = (float*)d_out;          // [8,64,32000] f32

    dim3 grid(NM, 2, VSPLIT);  // 1024 blocks, exactly one resident wave
    fused_kernel<<<grid, 128>>>(in, tmpl, spans, out);
}